// round 15
// baseline (speedup 1.0000x reference)
#include <cuda_runtime.h>
#include <cuda_fp16.h>
#include <math.h>
#include <stdint.h>

#define B_ 4
#define HW_ 65536
#define NTOK (B_*HW_)
#define DIM_ 128
#define HEADS_ 4

__device__ __half g_q[(size_t)NTOK*DIM_];
__device__ __half g_k[(size_t)NTOK*DIM_];
__device__ __half g_v[(size_t)NTOK*DIM_];
__device__ float  g_attn[B_*HEADS_*32*32];
__device__ float  g_attn_sm[B_*HEADS_*32*32];
__device__ float  g_ssq[B_*HEADS_*32];
__device__ float  g_ssk[B_*HEADS_*32];
__device__ __half g_M[B_*DIM_*DIM_];
__device__ __half g_pwh[4*128*128];   // [s][o][c]

__device__ __forceinline__ uint32_t pack2(float a, float b) {
    __half2 h = __floats2half2_rn(a, b);
    return *(uint32_t*)&h;
}
__device__ __forceinline__ void mma16(float* c, const uint32_t* a, uint32_t b0, uint32_t b1) {
    asm volatile(
        "mma.sync.aligned.m16n8k16.row.col.f32.f16.f16.f32 "
        "{%0,%1,%2,%3},{%4,%5,%6,%7},{%8,%9},{%0,%1,%2,%3};"
        : "+f"(c[0]), "+f"(c[1]), "+f"(c[2]), "+f"(c[3])
        : "r"(a[0]), "r"(a[1]), "r"(a[2]), "r"(a[3]), "r"(b0), "r"(b1));
}
__device__ __forceinline__ void ldsm4(uint32_t* r, const __half* p) {
    uint32_t a = (uint32_t)__cvta_generic_to_shared(p);
    asm volatile("ldmatrix.sync.aligned.m8n8.x4.shared.b16 {%0,%1,%2,%3},[%4];"
                 : "=r"(r[0]), "=r"(r[1]), "=r"(r[2]), "=r"(r[3]) : "r"(a));
}
__device__ __forceinline__ void ldsm4t(uint32_t* r, const __half* p) {
    uint32_t a = (uint32_t)__cvta_generic_to_shared(p);
    asm volatile("ldmatrix.sync.aligned.m8n8.x4.trans.shared.b16 {%0,%1,%2,%3},[%4];"
                 : "=r"(r[0]), "=r"(r[1]), "=r"(r[2]), "=r"(r[3]) : "r"(a));
}

// one zero kernel covering g_attn (16384) and g_ssq/g_ssk (512 each)
__global__ void zero_kernel() {
    int i = blockIdx.x*blockDim.x + threadIdx.x;
    if (i < B_*HEADS_*32*32) g_attn[i] = 0.f;
    if (i < B_*HEADS_*32) { g_ssq[i] = 0.f; g_ssk[i] = 0.f; }
}
__global__ void pw_prep_kernel(const float* __restrict__ pw_w) {
    int i = blockIdx.x*blockDim.x + threadIdx.x;
    int c = i & 127, o = (i >> 7) & 127, s = i >> 14;
    g_pwh[(s*128 + o)*128 + c] = __float2half(pw_w[(size_t)o*512 + c*4 + s]);
}

// ======================= fp16 GEMM (X resident, W double-buffer streamed) ====
#define LDX 136
template<bool BHALF, bool OUTHALF>
__device__ __forceinline__ void gemm_pass_h(const __half* Xs, __half* Ws,
                                            const float* Wf, const __half* Wh,
                                            __half* OutH, float* OutF,
                                            const float* bias)
{
    int tid = threadIdx.x, lane = tid & 31, warp = tid >> 5;
    int wm = (warp & 3) * 32, wn = (warp >> 2) * 64;
    int mat = lane >> 3, rr = lane & 7;
    int arow = (mat & 1)*8 + rr, acol8 = (mat >> 1)*8;
    float acc[2][8][4];
#pragma unroll
    for (int mt = 0; mt < 2; mt++)
#pragma unroll
        for (int nt = 0; nt < 8; nt++)
#pragma unroll
            for (int r = 0; r < 4; r++) acc[mt][nt][r] = 0.f;

    int kk = tid >> 4, n0 = (tid & 15) << 3;
    uint4 wreg; float4 w0, w1;
    if (BHALF) {
        wreg = *(const uint4*)(Wh + kk*128 + n0);
        *(uint4*)(Ws + kk*LDX + n0) = wreg;
    } else {
        w0 = *(const float4*)(Wf + kk*128 + n0);
        w1 = *(const float4*)(Wf + kk*128 + n0 + 4);
        *(uint4*)(Ws + kk*LDX + n0) =
            make_uint4(pack2(w0.x,w0.y), pack2(w0.z,w0.w), pack2(w1.x,w1.y), pack2(w1.z,w1.w));
    }
    __syncthreads();

    for (int c = 0; c < 8; c++) {
        if (c < 7) {
            if (BHALF) wreg = *(const uint4*)(Wh + (c+1)*2048 + kk*128 + n0);
            else { w0 = *(const float4*)(Wf + (c+1)*2048 + kk*128 + n0);
                   w1 = *(const float4*)(Wf + (c+1)*2048 + kk*128 + n0 + 4); }
        }
        const __half* Wb = Ws + (c & 1)*16*LDX;
        int k0 = c * 16;
        uint32_t a[2][4];
        ldsm4(a[0], Xs + (wm +      arow)*LDX + k0 + acol8);
        ldsm4(a[1], Xs + (wm + 16 + arow)*LDX + k0 + acol8);
        uint32_t b[8][2];
#pragma unroll
        for (int np = 0; np < 4; np++) {
            uint32_t r[4];
            ldsm4t(r, Wb + arow*LDX + wn + np*16 + acol8);
            b[np*2][0]=r[0]; b[np*2][1]=r[1]; b[np*2+1][0]=r[2]; b[np*2+1][1]=r[3];
        }
#pragma unroll
        for (int mt = 0; mt < 2; mt++)
#pragma unroll
            for (int nt = 0; nt < 8; nt++)
                mma16(acc[mt][nt], a[mt], b[nt][0], b[nt][1]);
        if (c < 7) {
            __half* Wn = Ws + ((c+1) & 1)*16*LDX;
            if (BHALF) *(uint4*)(Wn + kk*LDX + n0) = wreg;
            else *(uint4*)(Wn + kk*LDX + n0) =
                make_uint4(pack2(w0.x,w0.y), pack2(w0.z,w0.w), pack2(w1.x,w1.y), pack2(w1.z,w1.w));
        }
        __syncthreads();
    }
    int g = lane >> 2, kq = lane & 3;
#pragma unroll
    for (int mt = 0; mt < 2; mt++)
#pragma unroll
        for (int nt = 0; nt < 8; nt++) {
            int r = wm + mt*16 + g, cc = wn + nt*8 + kq*2;
            if (OUTHALF) {
                *(uint32_t*)(OutH + (size_t)r*128 + cc)     = pack2(acc[mt][nt][0], acc[mt][nt][1]);
                *(uint32_t*)(OutH + (size_t)(r+8)*128 + cc) = pack2(acc[mt][nt][2], acc[mt][nt][3]);
            } else {
                float b0v = bias[cc], b1v = bias[cc+1];
                float2 o0 = *(float2*)(OutF + (size_t)r*128 + cc);
                float2 o1 = *(float2*)(OutF + (size_t)(r+8)*128 + cc);
                o0.x += acc[mt][nt][0] + b0v; o0.y += acc[mt][nt][1] + b1v;
                o1.x += acc[mt][nt][2] + b0v; o1.y += acc[mt][nt][3] + b1v;
                *(float2*)(OutF + (size_t)r*128 + cc)     = o0;
                *(float2*)(OutF + (size_t)(r+8)*128 + cc) = o1;
            }
        }
}
#define GEMM_SMEM ((128*LDX + 32*LDX)*2)

__global__ void __launch_bounds__(256) qkv_kernel(const float* __restrict__ x,
                                                  const float* __restrict__ Wq,
                                                  const float* __restrict__ Wk,
                                                  const float* __restrict__ Wv)
{
    extern __shared__ __half smh[];
    __half* Xs = smh; __half* Ws = smh + 128*LDX;
    int tid = threadIdx.x;
    size_t tok0 = (size_t)blockIdx.x * 128;
    int t2 = tid >> 1, kh = (tid & 1) * 64;
    const float* src = x + (tok0 + t2)*128 + kh;
    __half* dst = Xs + t2*LDX + kh;
#pragma unroll
    for (int i = 0; i < 8; i++) {
        float4 a = *(const float4*)(src + i*8);
        float4 b = *(const float4*)(src + i*8 + 4);
        *(uint4*)(dst + i*8) = make_uint4(pack2(a.x,a.y), pack2(a.z,a.w),
                                          pack2(b.x,b.y), pack2(b.z,b.w));
    }
    __syncthreads();
    gemm_pass_h<false,true>(Xs, Ws, Wq, nullptr, g_q + tok0*128, nullptr, nullptr);
    gemm_pass_h<false,true>(Xs, Ws, Wk, nullptr, g_k + tok0*128, nullptr, nullptr);
    gemm_pass_h<false,true>(Xs, Ws, Wv, nullptr, g_v + tok0*128, nullptr, nullptr);
}

__global__ void __launch_bounds__(256) vm_kernel(const float* __restrict__ bproj,
                                                 float* __restrict__ out)
{
    extern __shared__ __half smh[];
    __half* Xs = smh; __half* Ws = smh + 128*LDX;
    int tid = threadIdx.x;
    size_t tok0 = (size_t)blockIdx.x * 128;
    int b = blockIdx.x >> 9;
    int t2 = tid >> 1, kh = (tid & 1) * 64;
    const __half* src = g_v + (tok0 + t2)*128 + kh;
    __half* dst = Xs + t2*LDX + kh;
#pragma unroll
    for (int i = 0; i < 8; i++) *(uint4*)(dst + i*8) = *(const uint4*)(src + i*8);
    __syncthreads();
    gemm_pass_h<true,false>(Xs, Ws, nullptr, g_M + (size_t)b*16384,
                            nullptr, out + tok0*128, bproj);
}

// ======= attn: unchanged from passing R14 ===================================
#define NCHUNK 16
#define LQH 40
__global__ void __launch_bounds__(256) attn_kernel()
{
    __shared__ __half qs[128*LQH];
    __shared__ __half ks[128*LQH];
    int b = blockIdx.z, h = blockIdx.y;
    int n0 = blockIdx.x * (HW_ / NCHUNK);
    int tid = threadIdx.x, lane = tid & 31, warp = tid >> 5;
    int mat = lane >> 3, rr = lane & 7;
    int r = tid >> 1, off = (tid & 1) * 16;
    int kt = warp * 16;
    float acc[2][4][4];
#pragma unroll
    for (int mt = 0; mt < 2; mt++)
#pragma unroll
        for (int nt = 0; nt < 4; nt++)
#pragma unroll
            for (int rg = 0; rg < 4; rg++) acc[mt][nt][rg] = 0.f;
    float2 ssq2[8], ssk2[8];
#pragma unroll
    for (int j = 0; j < 8; j++) { ssq2[j] = make_float2(0.f,0.f); ssk2[j] = make_float2(0.f,0.f); }

    for (int sub = 0; sub < (HW_/NCHUNK)/128; sub++) {
        int t0 = n0 + sub*128;
        size_t base = ((size_t)(b*HW_ + t0 + r))*128 + h*32 + off;
        uint4 q0 = *(const uint4*)(g_q + base);
        uint4 q1 = *(const uint4*)(g_q + base + 8);
        uint4 k0 = *(const uint4*)(g_k + base);
        uint4 k1 = *(const uint4*)(g_k + base + 8);
        *(uint4*)(qs + r*LQH + off)     = q0;
        *(uint4*)(qs + r*LQH + off + 8) = q1;
        *(uint4*)(ks + r*LQH + off)     = k0;
        *(uint4*)(ks + r*LQH + off + 8) = k1;
        {
            uint32_t uq[8] = {q0.x,q0.y,q0.z,q0.w,q1.x,q1.y,q1.z,q1.w};
            uint32_t uk[8] = {k0.x,k0.y,k0.z,k0.w,k1.x,k1.y,k1.z,k1.w};
#pragma unroll
            for (int j = 0; j < 8; j++) {
                float2 fq = __half22float2(*(__half2*)&uq[j]);
                float2 fk = __half22float2(*(__half2*)&uk[j]);
                ssq2[j].x += fq.x*fq.x; ssq2[j].y += fq.y*fq.y;
                ssk2[j].x += fk.x*fk.x; ssk2[j].y += fk.y*fk.y;
            }
        }
        __syncthreads();
        uint32_t a[2][4];
        ldsm4t(a[0], ks + (kt + (mat>>1)*8 + rr)*LQH + 0  + (mat&1)*8);
        ldsm4t(a[1], ks + (kt + (mat>>1)*8 + rr)*LQH + 16 + (mat&1)*8);
        uint32_t bfr[4][2];
#pragma unroll
        for (int eb = 0; eb < 2; eb++) {
            uint32_t r4[4];
            ldsm4t(r4, qs + (kt + (mat&1)*8 + rr)*LQH + eb*16 + (mat>>1)*8);
            bfr[eb*2][0]=r4[0]; bfr[eb*2][1]=r4[1]; bfr[eb*2+1][0]=r4[2]; bfr[eb*2+1][1]=r4[3];
        }
#pragma unroll
        for (int mt = 0; mt < 2; mt++)
#pragma unroll
            for (int nt = 0; nt < 4; nt++)
                mma16(acc[mt][nt], a[mt], bfr[nt][0], bfr[nt][1]);
        __syncthreads();
    }
    int bh = b*HEADS_ + h;
    int g2 = lane >> 2, e0 = (lane & 3)*2;
#pragma unroll
    for (int mt = 0; mt < 2; mt++)
#pragma unroll
        for (int nt = 0; nt < 4; nt++) {
            int d = mt*16 + g2, e = nt*8 + e0;
            atomicAdd(&g_attn[(bh*32 + d)*32 + e],       acc[mt][nt][0]);
            atomicAdd(&g_attn[(bh*32 + d)*32 + e + 1],   acc[mt][nt][1]);
            atomicAdd(&g_attn[(bh*32 + d+8)*32 + e],     acc[mt][nt][2]);
            atomicAdd(&g_attn[(bh*32 + d+8)*32 + e + 1], acc[mt][nt][3]);
        }
#pragma unroll
    for (int s = 2; s < 32; s <<= 1) {
#pragma unroll
        for (int j = 0; j < 8; j++) {
            ssq2[j].x += __shfl_xor_sync(~0u, ssq2[j].x, s);
            ssq2[j].y += __shfl_xor_sync(~0u, ssq2[j].y, s);
            ssk2[j].x += __shfl_xor_sync(~0u, ssk2[j].x, s);
            ssk2[j].y += __shfl_xor_sync(~0u, ssk2[j].y, s);
        }
    }
    if (lane < 2) {
#pragma unroll
        for (int j = 0; j < 8; j++) {
            atomicAdd(&g_ssq[bh*32 + off + 2*j],     ssq2[j].x);
            atomicAdd(&g_ssq[bh*32 + off + 2*j + 1], ssq2[j].y);
            atomicAdd(&g_ssk[bh*32 + off + 2*j],     ssk2[j].x);
            atomicAdd(&g_ssk[bh*32 + off + 2*j + 1], ssk2[j].y);
        }
    }
}

// ======================= softmax + M =========================================
__global__ void __launch_bounds__(1024) softmax_kernel(const float* __restrict__ rescale)
{
    int bh = blockIdx.x, h = bh & 3, tid = threadIdx.x;
    int d = tid >> 5, e = tid & 31;
    float nk = fmaxf(sqrtf(g_ssk[bh*32 + d]), 1e-12f);
    float nq = fmaxf(sqrtf(g_ssq[bh*32 + e]), 1e-12f);
    float val = g_attn[bh*1024 + d*32 + e] * rescale[h] / (nk*nq);
    float m = val;
#pragma unroll
    for (int off = 16; off > 0; off >>= 1) m = fmaxf(m, __shfl_xor_sync(~0u, m, off));
    float ex = expf(val - m);
    float s = ex;
#pragma unroll
    for (int off = 16; off > 0; off >>= 1) s += __shfl_xor_sync(~0u, s, off);
    g_attn_sm[bh*1024 + d*32 + e] = ex / s;
}

__global__ void __launch_bounds__(256) m_kernel(const float* __restrict__ Wproj)
{
    __shared__ float as[32*33];
    __shared__ float wp[32*128];
    int bh = blockIdx.x, b = bh >> 2, h = bh & 3, tid = threadIdx.x;
    for (int i = tid; i < 1024; i += 256) as[(i>>5)*33 + (i&31)] = g_attn_sm[bh*1024 + i];
    for (int i = tid; i < 1024; i += 256)
        ((float4*)wp)[i] = ((const float4*)(Wproj + (size_t)h*32*128))[i];
    __syncthreads();
    int c = tid & 127, eg = tid >> 7;
    for (int ee = 0; ee < 16; ee++) {
        int e = eg*16 + ee;
        float a = 0.f;
#pragma unroll
        for (int d = 0; d < 32; d++) a += as[d*33 + e] * wp[d*128 + c];
        g_M[(size_t)b*16384 + (h*32 + e)*128 + c] = __float2half(a);
    }
}

// ======= Gabor: register-window conv (vert once, horiz window reused 4 s) ===
#define GB_VT 6272
#define GB_TV 3584
#define LDG 40
#define GB_BYTES (GB_VT*4 + GB_TV*4 + 64*LDG*2 + 128*LDG*2)

__global__ void __launch_bounds__(256) gabor_kernel(const float* __restrict__ dw_w,
                                                    const float* __restrict__ dw_b,
                                                    const float* __restrict__ pw_b,
                                                    float* __restrict__ out)
{
    extern __shared__ float smf[];
    float* vt = smf;                                  // [14*14][32]
    float* tv = smf + GB_VT;                          // [8*14][32]
    __half* gh  = (__half*)(smf + GB_VT + GB_TV);     // [64][LDG]
    __half* pws = gh + 64*LDG;                        // [128][LDG]

    int b  = blockIdx.z, y0 = blockIdx.y << 3, x0 = blockIdx.x << 3;
    int tid = threadIdx.x, lane = tid & 31, warp = tid >> 5;
    int mat = lane >> 3, rr = lane & 7;
    int wn = warp * 16;
    int c  = tid & 31, xg = tid >> 5;   // conv-phase thread coords
    float acc[4][2][4];
#pragma unroll
    for (int mt = 0; mt < 4; mt++)
#pragma unroll
        for (int nt = 0; nt < 2; nt++)
#pragma unroll
            for (int r = 0; r < 4; r++) acc[mt][nt][r] = 0.f;

    float rowf[7];
#pragma unroll
    for (int i = 0; i < 7; i++) rowf[i] = dw_w[i*7 + 4];   // scale-independent

    for (int cg = 0; cg < 4; cg++) {
        int c0 = cg << 5;
        // v halo tile [14][14][32] (half -> float); prior cg's reads fenced by
        // the sync after its last mma
        for (int p = tid >> 5; p < 196; p += 8) {
            int row = p / 14, col = p % 14;
            int gy = y0 - 3 + row, gx = x0 - 3 + col;
            float val = 0.f;
            if ((unsigned)gy < 256u && (unsigned)gx < 256u)
                val = __half2float(g_v[((size_t)(b*HW_ + gy*256 + gx))*128 + c0 + c]);
            vt[(row*14 + col)*32 + c] = val;
        }
        __syncthreads();
        // vertical pass, register window: thread owns column (xi, c)
        for (int xi = xg; xi < 14; xi += 8) {
            float w[14];
#pragma unroll
            for (int i = 0; i < 14; i++) w[i] = vt[(i*14 + xi)*32 + c];
#pragma unroll
            for (int y = 0; y < 8; y++) {
                float sum = 0.f;
#pragma unroll
                for (int i = 0; i < 7; i++) sum += rowf[i]*w[y+i];
                tv[(y*14 + xi)*32 + c] = sum;
            }
        }
        __syncthreads();
        // horizontal window loaded ONCE per cg: thread owns row (y=xg, c)
        float w2[14];
#pragma unroll
        for (int xx = 0; xx < 14; xx++) w2[xx] = tv[(xg*14 + xx)*32 + c];

        for (int s = 0; s < 4; s++) {
            {   // horiz + bias + GELU from registers -> gh
                float colf[7];
#pragma unroll
                for (int j = 0; j < 7; j++) colf[j] = dw_w[s*49 + 28 + j];
                float bias = dw_b[(c0+c)*4 + s];
#pragma unroll
                for (int x = 0; x < 8; x++) {
                    float sum = bias;
#pragma unroll
                    for (int j = 0; j < 7; j++) sum += colf[j]*w2[x+j];
                    float g = 0.5f*sum*(1.f + erff(sum*0.70710678f));
                    gh[(xg*8 + x)*LDG + c] = __float2half(g);
                }
            }
            {   // stage pw (coalesced from prepped global): pws[o][c]
                int o = tid >> 1, off = (tid & 1)*16;
                const __half* src = g_pwh + ((s*128 + o)*128) + c0 + off;
                *(uint4*)(pws + o*LDG + off)     = *(const uint4*)src;
                *(uint4*)(pws + o*LDG + off + 8) = *(const uint4*)(src + 8);
            }
            __syncthreads();
#pragma unroll
            for (int kc = 0; kc < 2; kc++) {
                int k0 = kc*16;
                uint32_t a[4][4];
#pragma unroll
                for (int mt = 0; mt < 4; mt++)
                    ldsm4(a[mt], gh + (mt*16 + (mat&1)*8 + rr)*LDG + k0 + (mat>>1)*8);
                uint32_t r4[4];
                ldsm4(r4, pws + (wn + (mat>>1)*8 + rr)*LDG + k0 + (mat&1)*8);
#pragma unroll
                for (int mt = 0; mt < 4; mt++) {
                    mma16(acc[mt][0], a[mt], r4[0], r4[1]);
                    mma16(acc[mt][1], a[mt], r4[2], r4[3]);
                }
            }
            __syncthreads();   // mma reads done before next s overwrites gh/pws
        }
    }
    int g = lane >> 2, kq = lane & 3;
#pragma unroll
    for (int mt = 0; mt < 4; mt++)
#pragma unroll
        for (int nt = 0; nt < 2; nt++) {
            int cc = wn + nt*8 + kq*2;
            float pb0 = pw_b[cc], pb1 = pw_b[cc+1];
#pragma unroll
            for (int half = 0; half < 2; half++) {
                int pix = mt*16 + g + half*8;
                int y = pix >> 3, xx = pix & 7;
                size_t base = ((size_t)(b*HW_ + (y0+y)*256 + x0+xx))*128 + cc;
                float2 o0;
                o0.x = acc[mt][nt][half*2+0] + pb0;
                o0.y = acc[mt][nt][half*2+1] + pb1;
                *(float2*)(out + base) = o0;
            }
        }
}

// ---------------------------------------------------------------------------
extern "C" void kernel_launch(void* const* d_in, const int* in_sizes, int n_in,
                              void* d_out, int out_size)
{
    const float* x       = (const float*)d_in[0];
    const float* Wq      = (const float*)d_in[1];
    const float* Wk      = (const float*)d_in[2];
    const float* Wv      = (const float*)d_in[3];
    const float* rescale = (const float*)d_in[4];
    const float* Wproj   = (const float*)d_in[5];
    const float* bproj   = (const float*)d_in[6];
    const float* dw_w    = (const float*)d_in[7];
    const float* dw_b    = (const float*)d_in[8];
    const float* pw_w    = (const float*)d_in[9];
    const float* pw_b    = (const float*)d_in[10];
    float* out = (float*)d_out;

    cudaFuncSetAttribute(qkv_kernel, cudaFuncAttributeMaxDynamicSharedMemorySize, GEMM_SMEM);
    cudaFuncSetAttribute(vm_kernel,  cudaFuncAttributeMaxDynamicSharedMemorySize, GEMM_SMEM);
    cudaFuncSetAttribute(gabor_kernel, cudaFuncAttributeMaxDynamicSharedMemorySize, GB_BYTES);

    zero_kernel<<<64, 256>>>();                                   // idx 0
    pw_prep_kernel<<<256, 256>>>(pw_w);                           // idx 1
    qkv_kernel<<<NTOK/128, 256, GEMM_SMEM>>>(x, Wq, Wk, Wv);      // idx 2
    gabor_kernel<<<dim3(32, 32, B_), 256, GB_BYTES>>>(dw_w, dw_b, pw_b, out);  // idx 3 -> profiled
    attn_kernel<<<dim3(NCHUNK, HEADS_, B_), 256>>>();             // idx 4
    softmax_kernel<<<B_*HEADS_, 1024>>>(rescale);                 // idx 5
    m_kernel<<<B_*HEADS_, 256>>>(Wproj);                          // idx 6
    vm_kernel<<<NTOK/128, 256, GEMM_SMEM>>>(bproj, out);          // idx 7
}

// round 16
// speedup vs baseline: 1.2604x; 1.2604x over previous
#include <cuda_runtime.h>
#include <cuda_fp16.h>
#include <math.h>
#include <stdint.h>

#define B_ 4
#define HW_ 65536
#define NTOK (B_*HW_)
#define DIM_ 128
#define HEADS_ 4

__device__ __half g_q[(size_t)NTOK*DIM_];
__device__ __half g_k[(size_t)NTOK*DIM_];
__device__ __half g_v[(size_t)NTOK*DIM_];
__device__ float  g_attn[B_*HEADS_*32*32];
__device__ float  g_attn_sm[B_*HEADS_*32*32];
__device__ float  g_ssq[B_*HEADS_*32];
__device__ float  g_ssk[B_*HEADS_*32];
__device__ __half g_M[B_*DIM_*DIM_];
__device__ __half g_pwh[4*128*128];   // [s][o][c]

__device__ __forceinline__ uint32_t pack2(float a, float b) {
    __half2 h = __floats2half2_rn(a, b);
    return *(uint32_t*)&h;
}
__device__ __forceinline__ void mma16(float* c, const uint32_t* a, uint32_t b0, uint32_t b1) {
    asm volatile(
        "mma.sync.aligned.m16n8k16.row.col.f32.f16.f16.f32 "
        "{%0,%1,%2,%3},{%4,%5,%6,%7},{%8,%9},{%0,%1,%2,%3};"
        : "+f"(c[0]), "+f"(c[1]), "+f"(c[2]), "+f"(c[3])
        : "r"(a[0]), "r"(a[1]), "r"(a[2]), "r"(a[3]), "r"(b0), "r"(b1));
}
__device__ __forceinline__ void ldsm4(uint32_t* r, const __half* p) {
    uint32_t a = (uint32_t)__cvta_generic_to_shared(p);
    asm volatile("ldmatrix.sync.aligned.m8n8.x4.shared.b16 {%0,%1,%2,%3},[%4];"
                 : "=r"(r[0]), "=r"(r[1]), "=r"(r[2]), "=r"(r[3]) : "r"(a));
}
__device__ __forceinline__ void ldsm4t(uint32_t* r, const __half* p) {
    uint32_t a = (uint32_t)__cvta_generic_to_shared(p);
    asm volatile("ldmatrix.sync.aligned.m8n8.x4.trans.shared.b16 {%0,%1,%2,%3},[%4];"
                 : "=r"(r[0]), "=r"(r[1]), "=r"(r[2]), "=r"(r[3]) : "r"(a));
}

__global__ void zero_kernel() {
    int i = blockIdx.x*blockDim.x + threadIdx.x;
    if (i < B_*HEADS_*32*32) g_attn[i] = 0.f;
    if (i < B_*HEADS_*32) { g_ssq[i] = 0.f; g_ssk[i] = 0.f; }
}
__global__ void pw_prep_kernel(const float* __restrict__ pw_w) {
    int i = blockIdx.x*blockDim.x + threadIdx.x;
    int c = i & 127, o = (i >> 7) & 127, s = i >> 14;
    g_pwh[(s*128 + o)*128 + c] = __float2half(pw_w[(size_t)o*512 + c*4 + s]);
}

// ======================= fp16 GEMM (X resident, W double-buffer streamed) ====
#define LDX 136
template<bool BHALF, bool OUTHALF>
__device__ __forceinline__ void gemm_pass_h(const __half* Xs, __half* Ws,
                                            const float* Wf, const __half* Wh,
                                            __half* OutH, float* OutF,
                                            const float* bias)
{
    int tid = threadIdx.x, lane = tid & 31, warp = tid >> 5;
    int wm = (warp & 3) * 32, wn = (warp >> 2) * 64;
    int mat = lane >> 3, rr = lane & 7;
    int arow = (mat & 1)*8 + rr, acol8 = (mat >> 1)*8;
    float acc[2][8][4];
#pragma unroll
    for (int mt = 0; mt < 2; mt++)
#pragma unroll
        for (int nt = 0; nt < 8; nt++)
#pragma unroll
            for (int r = 0; r < 4; r++) acc[mt][nt][r] = 0.f;

    int kk = tid >> 4, n0 = (tid & 15) << 3;
    uint4 wreg; float4 w0, w1;
    if (BHALF) {
        wreg = *(const uint4*)(Wh + kk*128 + n0);
        *(uint4*)(Ws + kk*LDX + n0) = wreg;
    } else {
        w0 = *(const float4*)(Wf + kk*128 + n0);
        w1 = *(const float4*)(Wf + kk*128 + n0 + 4);
        *(uint4*)(Ws + kk*LDX + n0) =
            make_uint4(pack2(w0.x,w0.y), pack2(w0.z,w0.w), pack2(w1.x,w1.y), pack2(w1.z,w1.w));
    }
    __syncthreads();

    for (int c = 0; c < 8; c++) {
        if (c < 7) {
            if (BHALF) wreg = *(const uint4*)(Wh + (c+1)*2048 + kk*128 + n0);
            else { w0 = *(const float4*)(Wf + (c+1)*2048 + kk*128 + n0);
                   w1 = *(const float4*)(Wf + (c+1)*2048 + kk*128 + n0 + 4); }
        }
        const __half* Wb = Ws + (c & 1)*16*LDX;
        int k0 = c * 16;
        uint32_t a[2][4];
        ldsm4(a[0], Xs + (wm +      arow)*LDX + k0 + acol8);
        ldsm4(a[1], Xs + (wm + 16 + arow)*LDX + k0 + acol8);
        uint32_t b[8][2];
#pragma unroll
        for (int np = 0; np < 4; np++) {
            uint32_t r[4];
            ldsm4t(r, Wb + arow*LDX + wn + np*16 + acol8);
            b[np*2][0]=r[0]; b[np*2][1]=r[1]; b[np*2+1][0]=r[2]; b[np*2+1][1]=r[3];
        }
#pragma unroll
        for (int mt = 0; mt < 2; mt++)
#pragma unroll
            for (int nt = 0; nt < 8; nt++)
                mma16(acc[mt][nt], a[mt], b[nt][0], b[nt][1]);
        if (c < 7) {
            __half* Wn = Ws + ((c+1) & 1)*16*LDX;
            if (BHALF) *(uint4*)(Wn + kk*LDX + n0) = wreg;
            else *(uint4*)(Wn + kk*LDX + n0) =
                make_uint4(pack2(w0.x,w0.y), pack2(w0.z,w0.w), pack2(w1.x,w1.y), pack2(w1.z,w1.w));
        }
        __syncthreads();
    }
    int g = lane >> 2, kq = lane & 3;
#pragma unroll
    for (int mt = 0; mt < 2; mt++)
#pragma unroll
        for (int nt = 0; nt < 8; nt++) {
            int r = wm + mt*16 + g, cc = wn + nt*8 + kq*2;
            if (OUTHALF) {
                *(uint32_t*)(OutH + (size_t)r*128 + cc)     = pack2(acc[mt][nt][0], acc[mt][nt][1]);
                *(uint32_t*)(OutH + (size_t)(r+8)*128 + cc) = pack2(acc[mt][nt][2], acc[mt][nt][3]);
            } else {
                float b0v = bias[cc], b1v = bias[cc+1];
                float2 o0 = *(float2*)(OutF + (size_t)r*128 + cc);
                float2 o1 = *(float2*)(OutF + (size_t)(r+8)*128 + cc);
                o0.x += acc[mt][nt][0] + b0v; o0.y += acc[mt][nt][1] + b1v;
                o1.x += acc[mt][nt][2] + b0v; o1.y += acc[mt][nt][3] + b1v;
                *(float2*)(OutF + (size_t)r*128 + cc)     = o0;
                *(float2*)(OutF + (size_t)(r+8)*128 + cc) = o1;
            }
        }
}
#define GEMM_SMEM ((128*LDX + 32*LDX)*2)

__global__ void __launch_bounds__(256) qkv_kernel(const float* __restrict__ x,
                                                  const float* __restrict__ Wq,
                                                  const float* __restrict__ Wk,
                                                  const float* __restrict__ Wv)
{
    extern __shared__ __half smh[];
    __half* Xs = smh; __half* Ws = smh + 128*LDX;
    int tid = threadIdx.x;
    size_t tok0 = (size_t)blockIdx.x * 128;
    int t2 = tid >> 1, kh = (tid & 1) * 64;
    const float* src = x + (tok0 + t2)*128 + kh;
    __half* dst = Xs + t2*LDX + kh;
#pragma unroll
    for (int i = 0; i < 8; i++) {
        float4 a = *(const float4*)(src + i*8);
        float4 b = *(const float4*)(src + i*8 + 4);
        *(uint4*)(dst + i*8) = make_uint4(pack2(a.x,a.y), pack2(a.z,a.w),
                                          pack2(b.x,b.y), pack2(b.z,b.w));
    }
    __syncthreads();
    gemm_pass_h<false,true>(Xs, Ws, Wq, nullptr, g_q + tok0*128, nullptr, nullptr);
    gemm_pass_h<false,true>(Xs, Ws, Wk, nullptr, g_k + tok0*128, nullptr, nullptr);
    gemm_pass_h<false,true>(Xs, Ws, Wv, nullptr, g_v + tok0*128, nullptr, nullptr);
}

__global__ void __launch_bounds__(256) vm_kernel(const float* __restrict__ bproj,
                                                 float* __restrict__ out)
{
    extern __shared__ __half smh[];
    __half* Xs = smh; __half* Ws = smh + 128*LDX;
    int tid = threadIdx.x;
    size_t tok0 = (size_t)blockIdx.x * 128;
    int b = blockIdx.x >> 9;
    int t2 = tid >> 1, kh = (tid & 1) * 64;
    const __half* src = g_v + (tok0 + t2)*128 + kh;
    __half* dst = Xs + t2*LDX + kh;
#pragma unroll
    for (int i = 0; i < 8; i++) *(uint4*)(dst + i*8) = *(const uint4*)(src + i*8);
    __syncthreads();
    gemm_pass_h<true,false>(Xs, Ws, nullptr, g_M + (size_t)b*16384,
                            nullptr, out + tok0*128, bproj);
}

// ======= attn: unchanged from passing R14/R15 ================================
#define NCHUNK 16
#define LQH 40
__global__ void __launch_bounds__(256) attn_kernel()
{
    __shared__ __half qs[128*LQH];
    __shared__ __half ks[128*LQH];
    int b = blockIdx.z, h = blockIdx.y;
    int n0 = blockIdx.x * (HW_ / NCHUNK);
    int tid = threadIdx.x, lane = tid & 31, warp = tid >> 5;
    int mat = lane >> 3, rr = lane & 7;
    int r = tid >> 1, off = (tid & 1) * 16;
    int kt = warp * 16;
    float acc[2][4][4];
#pragma unroll
    for (int mt = 0; mt < 2; mt++)
#pragma unroll
        for (int nt = 0; nt < 4; nt++)
#pragma unroll
            for (int rg = 0; rg < 4; rg++) acc[mt][nt][rg] = 0.f;
    float2 ssq2[8], ssk2[8];
#pragma unroll
    for (int j = 0; j < 8; j++) { ssq2[j] = make_float2(0.f,0.f); ssk2[j] = make_float2(0.f,0.f); }

    for (int sub = 0; sub < (HW_/NCHUNK)/128; sub++) {
        int t0 = n0 + sub*128;
        size_t base = ((size_t)(b*HW_ + t0 + r))*128 + h*32 + off;
        uint4 q0 = *(const uint4*)(g_q + base);
        uint4 q1 = *(const uint4*)(g_q + base + 8);
        uint4 k0 = *(const uint4*)(g_k + base);
        uint4 k1 = *(const uint4*)(g_k + base + 8);
        *(uint4*)(qs + r*LQH + off)     = q0;
        *(uint4*)(qs + r*LQH + off + 8) = q1;
        *(uint4*)(ks + r*LQH + off)     = k0;
        *(uint4*)(ks + r*LQH + off + 8) = k1;
        {
            uint32_t uq[8] = {q0.x,q0.y,q0.z,q0.w,q1.x,q1.y,q1.z,q1.w};
            uint32_t uk[8] = {k0.x,k0.y,k0.z,k0.w,k1.x,k1.y,k1.z,k1.w};
#pragma unroll
            for (int j = 0; j < 8; j++) {
                float2 fq = __half22float2(*(__half2*)&uq[j]);
                float2 fk = __half22float2(*(__half2*)&uk[j]);
                ssq2[j].x += fq.x*fq.x; ssq2[j].y += fq.y*fq.y;
                ssk2[j].x += fk.x*fk.x; ssk2[j].y += fk.y*fk.y;
            }
        }
        __syncthreads();
        uint32_t a[2][4];
        ldsm4t(a[0], ks + (kt + (mat>>1)*8 + rr)*LQH + 0  + (mat&1)*8);
        ldsm4t(a[1], ks + (kt + (mat>>1)*8 + rr)*LQH + 16 + (mat&1)*8);
        uint32_t bfr[4][2];
#pragma unroll
        for (int eb = 0; eb < 2; eb++) {
            uint32_t r4[4];
            ldsm4t(r4, qs + (kt + (mat&1)*8 + rr)*LQH + eb*16 + (mat>>1)*8);
            bfr[eb*2][0]=r4[0]; bfr[eb*2][1]=r4[1]; bfr[eb*2+1][0]=r4[2]; bfr[eb*2+1][1]=r4[3];
        }
#pragma unroll
        for (int mt = 0; mt < 2; mt++)
#pragma unroll
            for (int nt = 0; nt < 4; nt++)
                mma16(acc[mt][nt], a[mt], bfr[nt][0], bfr[nt][1]);
        __syncthreads();
    }
    int bh = b*HEADS_ + h;
    int g2 = lane >> 2, e0 = (lane & 3)*2;
#pragma unroll
    for (int mt = 0; mt < 2; mt++)
#pragma unroll
        for (int nt = 0; nt < 4; nt++) {
            int d = mt*16 + g2, e = nt*8 + e0;
            atomicAdd(&g_attn[(bh*32 + d)*32 + e],       acc[mt][nt][0]);
            atomicAdd(&g_attn[(bh*32 + d)*32 + e + 1],   acc[mt][nt][1]);
            atomicAdd(&g_attn[(bh*32 + d+8)*32 + e],     acc[mt][nt][2]);
            atomicAdd(&g_attn[(bh*32 + d+8)*32 + e + 1], acc[mt][nt][3]);
        }
#pragma unroll
    for (int s = 2; s < 32; s <<= 1) {
#pragma unroll
        for (int j = 0; j < 8; j++) {
            ssq2[j].x += __shfl_xor_sync(~0u, ssq2[j].x, s);
            ssq2[j].y += __shfl_xor_sync(~0u, ssq2[j].y, s);
            ssk2[j].x += __shfl_xor_sync(~0u, ssk2[j].x, s);
            ssk2[j].y += __shfl_xor_sync(~0u, ssk2[j].y, s);
        }
    }
    if (lane < 2) {
#pragma unroll
        for (int j = 0; j < 8; j++) {
            atomicAdd(&g_ssq[bh*32 + off + 2*j],     ssq2[j].x);
            atomicAdd(&g_ssq[bh*32 + off + 2*j + 1], ssq2[j].y);
            atomicAdd(&g_ssk[bh*32 + off + 2*j],     ssk2[j].x);
            atomicAdd(&g_ssk[bh*32 + off + 2*j + 1], ssk2[j].y);
        }
    }
}

// ======================= softmax + M =========================================
__global__ void __launch_bounds__(1024) softmax_kernel(const float* __restrict__ rescale)
{
    int bh = blockIdx.x, h = bh & 3, tid = threadIdx.x;
    int d = tid >> 5, e = tid & 31;
    float nk = fmaxf(sqrtf(g_ssk[bh*32 + d]), 1e-12f);
    float nq = fmaxf(sqrtf(g_ssq[bh*32 + e]), 1e-12f);
    float val = g_attn[bh*1024 + d*32 + e] * rescale[h] / (nk*nq);
    float m = val;
#pragma unroll
    for (int off = 16; off > 0; off >>= 1) m = fmaxf(m, __shfl_xor_sync(~0u, m, off));
    float ex = expf(val - m);
    float s = ex;
#pragma unroll
    for (int off = 16; off > 0; off >>= 1) s += __shfl_xor_sync(~0u, s, off);
    g_attn_sm[bh*1024 + d*32 + e] = ex / s;
}

__global__ void __launch_bounds__(256) m_kernel(const float* __restrict__ Wproj)
{
    __shared__ float as[32*33];
    __shared__ float wp[32*128];
    int bh = blockIdx.x, b = bh >> 2, h = bh & 3, tid = threadIdx.x;
    for (int i = tid; i < 1024; i += 256) as[(i>>5)*33 + (i&31)] = g_attn_sm[bh*1024 + i];
    for (int i = tid; i < 1024; i += 256)
        ((float4*)wp)[i] = ((const float4*)(Wproj + (size_t)h*32*128))[i];
    __syncthreads();
    int c = tid & 127, eg = tid >> 7;
    for (int ee = 0; ee < 16; ee++) {
        int e = eg*16 + ee;
        float a = 0.f;
#pragma unroll
        for (int d = 0; d < 32; d++) a += as[d*33 + e] * wp[d*128 + c];
        g_M[(size_t)b*16384 + (h*32 + e)*128 + c] = __float2half(a);
    }
}

// ======= Gabor v3: div-free vectorized halo + double-buffered gh/pws ========
#define GB_VT 6272            // floats: [196][32]
#define GB_TV 3584            // floats: [112][32]
#define LDG 40
#define GB_BYTES (GB_VT*4 + GB_TV*4 + 2*64*LDG*2 + 2*128*LDG*2)

__global__ void __launch_bounds__(256) gabor_kernel(const float* __restrict__ dw_w,
                                                    const float* __restrict__ dw_b,
                                                    const float* __restrict__ pw_b,
                                                    float* __restrict__ out)
{
    extern __shared__ float smf[];
    float* vt = smf;                                  // [14*14][32]
    float* tv = smf + GB_VT;                          // [8*14][32]
    __half* gh  = (__half*)(smf + GB_VT + GB_TV);     // [2][64][LDG]
    __half* pws = gh + 2*64*LDG;                      // [2][128][LDG]

    int b  = blockIdx.z, y0 = blockIdx.y << 3, x0 = blockIdx.x << 3;
    int tid = threadIdx.x, lane = tid & 31, warp = tid >> 5;
    int mat = lane >> 3, rr = lane & 7;
    int wn = warp * 16;
    int c  = tid & 31, xg = tid >> 5;         // conv coords
    int cp = tid & 15, colslot = tid >> 4;    // halo coords (colslot 0..15, 14 used)
    float acc[4][2][4];
#pragma unroll
    for (int mt = 0; mt < 4; mt++)
#pragma unroll
        for (int nt = 0; nt < 2; nt++)
#pragma unroll
            for (int r = 0; r < 4; r++) acc[mt][nt][r] = 0.f;

    float rowf[7];
#pragma unroll
    for (int i = 0; i < 7; i++) rowf[i] = dw_w[i*7 + 4];   // scale-independent

    int gx = x0 - 3 + colslot;
    bool xok = (colslot < 14) && ((unsigned)gx < 256u);
    bool slotok = (colslot < 14);

    for (int cg = 0; cg < 4; cg++) {
        int c0 = cg << 5;
        // --- halo [14][14][32], div-free, half2 -> float2 ---
        {
            const __half* vbase = g_v + ((size_t)(b*HW_ + (y0-3)*256 + gx))*128 + c0 + 2*cp;
            float* sdst = &vt[colslot*32 + 2*cp];
#pragma unroll
            for (int row = 0; row < 14; row++) {
                int gy = y0 - 3 + row;
                float2 v = make_float2(0.f, 0.f);
                if (xok && (unsigned)gy < 256u)
                    v = __half22float2(*(const __half2*)(vbase + (size_t)row*256*128));
                if (slotok) *(float2*)(sdst + row*14*32) = v;
            }
        }
        __syncthreads();
        // --- vertical pass, register window ---
        for (int xi = xg; xi < 14; xi += 8) {
            float w[14];
#pragma unroll
            for (int i = 0; i < 14; i++) w[i] = vt[(i*14 + xi)*32 + c];
#pragma unroll
            for (int y = 0; y < 8; y++) {
                float sum = 0.f;
#pragma unroll
                for (int i = 0; i < 7; i++) sum += rowf[i]*w[y+i];
                tv[(y*14 + xi)*32 + c] = sum;
            }
        }
        __syncthreads();
        // --- horizontal window loaded once per cg ---
        float w2[14];
#pragma unroll
        for (int xx = 0; xx < 14; xx++) w2[xx] = tv[(xg*14 + xx)*32 + c];

        for (int s = 0; s < 4; s++) {
            int p = s & 1;
            __half* ghb = gh  + p*64*LDG;
            __half* pwb = pws + p*128*LDG;
            {   // horiz + bias + exact GELU from registers -> ghb
                float colf[7];
#pragma unroll
                for (int j = 0; j < 7; j++) colf[j] = dw_w[s*49 + 28 + j];
                float bias = dw_b[(c0+c)*4 + s];
#pragma unroll
                for (int x = 0; x < 8; x++) {
                    float sum = bias;
#pragma unroll
                    for (int j = 0; j < 7; j++) sum += colf[j]*w2[x+j];
                    float g = 0.5f*sum*(1.f + erff(sum*0.70710678f));
                    ghb[(xg*8 + x)*LDG + c] = __float2half(g);
                }
            }
            {   // stage pw (coalesced): pwb[o][c]
                int o = tid >> 1, off = (tid & 1)*16;
                const __half* src = g_pwh + ((s*128 + o)*128) + c0 + off;
                *(uint4*)(pwb + o*LDG + off)     = *(const uint4*)src;
                *(uint4*)(pwb + o*LDG + off + 8) = *(const uint4*)(src + 8);
            }
            __syncthreads();          // single barrier per scale (double-buffered)
#pragma unroll
            for (int kc = 0; kc < 2; kc++) {
                int k0 = kc*16;
                uint32_t a[4][4];
#pragma unroll
                for (int mt = 0; mt < 4; mt++)
                    ldsm4(a[mt], ghb + (mt*16 + (mat&1)*8 + rr)*LDG + k0 + (mat>>1)*8);
                uint32_t r4[4];
                ldsm4(r4, pwb + (wn + (mat>>1)*8 + rr)*LDG + k0 + (mat&1)*8);
#pragma unroll
                for (int mt = 0; mt < 4; mt++) {
                    mma16(acc[mt][0], a[mt], r4[0], r4[1]);
                    mma16(acc[mt][1], a[mt], r4[2], r4[3]);
                }
            }
        }
        __syncthreads();   // last s's ldsm done before next cg rewrites vt/tv/buffers
    }
    int g = lane >> 2, kq = lane & 3;
#pragma unroll
    for (int mt = 0; mt < 4; mt++)
#pragma unroll
        for (int nt = 0; nt < 2; nt++) {
            int cc = wn + nt*8 + kq*2;
            float pb0 = pw_b[cc], pb1 = pw_b[cc+1];
#pragma unroll
            for (int half = 0; half < 2; half++) {
                int pix = mt*16 + g + half*8;
                int y = pix >> 3, xx = pix & 7;
                size_t base = ((size_t)(b*HW_ + (y0+y)*256 + x0+xx))*128 + cc;
                float2 o0;
                o0.x = acc[mt][nt][half*2+0] + pb0;
                o0.y = acc[mt][nt][half*2+1] + pb1;
                *(float2*)(out + base) = o0;
            }
        }
}

// ---------------------------------------------------------------------------
extern "C" void kernel_launch(void* const* d_in, const int* in_sizes, int n_in,
                              void* d_out, int out_size)
{
    const float* x       = (const float*)d_in[0];
    const float* Wq      = (const float*)d_in[1];
    const float* Wk      = (const float*)d_in[2];
    const float* Wv      = (const float*)d_in[3];
    const float* rescale = (const float*)d_in[4];
    const float* Wproj   = (const float*)d_in[5];
    const float* bproj   = (const float*)d_in[6];
    const float* dw_w    = (const float*)d_in[7];
    const float* dw_b    = (const float*)d_in[8];
    const float* pw_w    = (const float*)d_in[9];
    const float* pw_b    = (const float*)d_in[10];
    float* out = (float*)d_out;

    cudaFuncSetAttribute(qkv_kernel, cudaFuncAttributeMaxDynamicSharedMemorySize, GEMM_SMEM);
    cudaFuncSetAttribute(vm_kernel,  cudaFuncAttributeMaxDynamicSharedMemorySize, GEMM_SMEM);
    cudaFuncSetAttribute(gabor_kernel, cudaFuncAttributeMaxDynamicSharedMemorySize, GB_BYTES);

    zero_kernel<<<64, 256>>>();                                   // idx 0
    pw_prep_kernel<<<256, 256>>>(pw_w);                           // idx 1
    qkv_kernel<<<NTOK/128, 256, GEMM_SMEM>>>(x, Wq, Wk, Wv);      // idx 2
    gabor_kernel<<<dim3(32, 32, B_), 256, GB_BYTES>>>(dw_w, dw_b, pw_b, out);  // idx 3 -> profiled
    attn_kernel<<<dim3(NCHUNK, HEADS_, B_), 256>>>();             // idx 4
    softmax_kernel<<<B_*HEADS_, 1024>>>(rescale);                 // idx 5
    m_kernel<<<B_*HEADS_, 256>>>(Wproj);                          // idx 6
    vm_kernel<<<NTOK/128, 256, GEMM_SMEM>>>(bproj, out);          // idx 7
}

// round 17
// speedup vs baseline: 1.5845x; 1.2572x over previous
#include <cuda_runtime.h>
#include <cuda_fp16.h>
#include <math.h>
#include <stdint.h>

#define B_ 4
#define HW_ 65536
#define NTOK (B_*HW_)
#define DIM_ 128
#define HEADS_ 4

__device__ __half g_q[(size_t)NTOK*DIM_];
__device__ __half g_k[(size_t)NTOK*DIM_];
__device__ __half g_v[(size_t)NTOK*DIM_];
__device__ float  g_attn[B_*HEADS_*32*32];
__device__ float  g_attn_sm[B_*HEADS_*32*32];
__device__ float  g_ssq[B_*HEADS_*32];
__device__ float  g_ssk[B_*HEADS_*32];
__device__ __half g_M[B_*DIM_*DIM_];
__device__ __half g_pwh[4*128*128];   // [s][o][c]

__device__ __forceinline__ uint32_t pack2(float a, float b) {
    __half2 h = __floats2half2_rn(a, b);
    return *(uint32_t*)&h;
}
__device__ __forceinline__ float tanh_fast(float x) {
    float y; asm("tanh.approx.f32 %0, %1;" : "=f"(y) : "f"(x)); return y;
}
__device__ __forceinline__ void mma16(float* c, const uint32_t* a, uint32_t b0, uint32_t b1) {
    asm volatile(
        "mma.sync.aligned.m16n8k16.row.col.f32.f16.f16.f32 "
        "{%0,%1,%2,%3},{%4,%5,%6,%7},{%8,%9},{%0,%1,%2,%3};"
        : "+f"(c[0]), "+f"(c[1]), "+f"(c[2]), "+f"(c[3])
        : "r"(a[0]), "r"(a[1]), "r"(a[2]), "r"(a[3]), "r"(b0), "r"(b1));
}
__device__ __forceinline__ void ldsm4(uint32_t* r, const __half* p) {
    uint32_t a = (uint32_t)__cvta_generic_to_shared(p);
    asm volatile("ldmatrix.sync.aligned.m8n8.x4.shared.b16 {%0,%1,%2,%3},[%4];"
                 : "=r"(r[0]), "=r"(r[1]), "=r"(r[2]), "=r"(r[3]) : "r"(a));
}
__device__ __forceinline__ void ldsm4t(uint32_t* r, const __half* p) {
    uint32_t a = (uint32_t)__cvta_generic_to_shared(p);
    asm volatile("ldmatrix.sync.aligned.m8n8.x4.trans.shared.b16 {%0,%1,%2,%3},[%4];"
                 : "=r"(r[0]), "=r"(r[1]), "=r"(r[2]), "=r"(r[3]) : "r"(a));
}

__global__ void zero_kernel() {
    int i = blockIdx.x*blockDim.x + threadIdx.x;
    if (i < B_*HEADS_*32*32) g_attn[i] = 0.f;
    if (i < B_*HEADS_*32) { g_ssq[i] = 0.f; g_ssk[i] = 0.f; }
}
__global__ void pw_prep_kernel(const float* __restrict__ pw_w) {
    int i = blockIdx.x*blockDim.x + threadIdx.x;
    int c = i & 127, o = (i >> 7) & 127, s = i >> 14;
    g_pwh[(s*128 + o)*128 + c] = __float2half(pw_w[(size_t)o*512 + c*4 + s]);
}

// ======================= fp16 GEMM (X resident, W double-buffer streamed) ====
#define LDX 136
template<bool BHALF, bool OUTHALF>
__device__ __forceinline__ void gemm_pass_h(const __half* Xs, __half* Ws,
                                            const float* Wf, const __half* Wh,
                                            __half* OutH, float* OutF,
                                            const float* bias)
{
    int tid = threadIdx.x, lane = tid & 31, warp = tid >> 5;
    int wm = (warp & 3) * 32, wn = (warp >> 2) * 64;
    int mat = lane >> 3, rr = lane & 7;
    int arow = (mat & 1)*8 + rr, acol8 = (mat >> 1)*8;
    float acc[2][8][4];
#pragma unroll
    for (int mt = 0; mt < 2; mt++)
#pragma unroll
        for (int nt = 0; nt < 8; nt++)
#pragma unroll
            for (int r = 0; r < 4; r++) acc[mt][nt][r] = 0.f;

    int kk = tid >> 4, n0 = (tid & 15) << 3;
    uint4 wreg; float4 w0, w1;
    if (BHALF) {
        wreg = *(const uint4*)(Wh + kk*128 + n0);
        *(uint4*)(Ws + kk*LDX + n0) = wreg;
    } else {
        w0 = *(const float4*)(Wf + kk*128 + n0);
        w1 = *(const float4*)(Wf + kk*128 + n0 + 4);
        *(uint4*)(Ws + kk*LDX + n0) =
            make_uint4(pack2(w0.x,w0.y), pack2(w0.z,w0.w), pack2(w1.x,w1.y), pack2(w1.z,w1.w));
    }
    __syncthreads();

    for (int c = 0; c < 8; c++) {
        if (c < 7) {
            if (BHALF) wreg = *(const uint4*)(Wh + (c+1)*2048 + kk*128 + n0);
            else { w0 = *(const float4*)(Wf + (c+1)*2048 + kk*128 + n0);
                   w1 = *(const float4*)(Wf + (c+1)*2048 + kk*128 + n0 + 4); }
        }
        const __half* Wb = Ws + (c & 1)*16*LDX;
        int k0 = c * 16;
        uint32_t a[2][4];
        ldsm4(a[0], Xs + (wm +      arow)*LDX + k0 + acol8);
        ldsm4(a[1], Xs + (wm + 16 + arow)*LDX + k0 + acol8);
        uint32_t b[8][2];
#pragma unroll
        for (int np = 0; np < 4; np++) {
            uint32_t r[4];
            ldsm4t(r, Wb + arow*LDX + wn + np*16 + acol8);
            b[np*2][0]=r[0]; b[np*2][1]=r[1]; b[np*2+1][0]=r[2]; b[np*2+1][1]=r[3];
        }
#pragma unroll
        for (int mt = 0; mt < 2; mt++)
#pragma unroll
            for (int nt = 0; nt < 8; nt++)
                mma16(acc[mt][nt], a[mt], b[nt][0], b[nt][1]);
        if (c < 7) {
            __half* Wn = Ws + ((c+1) & 1)*16*LDX;
            if (BHALF) *(uint4*)(Wn + kk*LDX + n0) = wreg;
            else *(uint4*)(Wn + kk*LDX + n0) =
                make_uint4(pack2(w0.x,w0.y), pack2(w0.z,w0.w), pack2(w1.x,w1.y), pack2(w1.z,w1.w));
        }
        __syncthreads();
    }
    int g = lane >> 2, kq = lane & 3;
#pragma unroll
    for (int mt = 0; mt < 2; mt++)
#pragma unroll
        for (int nt = 0; nt < 8; nt++) {
            int r = wm + mt*16 + g, cc = wn + nt*8 + kq*2;
            if (OUTHALF) {
                *(uint32_t*)(OutH + (size_t)r*128 + cc)     = pack2(acc[mt][nt][0], acc[mt][nt][1]);
                *(uint32_t*)(OutH + (size_t)(r+8)*128 + cc) = pack2(acc[mt][nt][2], acc[mt][nt][3]);
            } else {
                float b0v = bias[cc], b1v = bias[cc+1];
                float2 o0 = *(float2*)(OutF + (size_t)r*128 + cc);
                float2 o1 = *(float2*)(OutF + (size_t)(r+8)*128 + cc);
                o0.x += acc[mt][nt][0] + b0v; o0.y += acc[mt][nt][1] + b1v;
                o1.x += acc[mt][nt][2] + b0v; o1.y += acc[mt][nt][3] + b1v;
                *(float2*)(OutF + (size_t)r*128 + cc)     = o0;
                *(float2*)(OutF + (size_t)(r+8)*128 + cc) = o1;
            }
        }
}
#define GEMM_SMEM ((128*LDX + 32*LDX)*2)

__global__ void __launch_bounds__(256) qkv_kernel(const float* __restrict__ x,
                                                  const float* __restrict__ Wq,
                                                  const float* __restrict__ Wk,
                                                  const float* __restrict__ Wv)
{
    extern __shared__ __half smh[];
    __half* Xs = smh; __half* Ws = smh + 128*LDX;
    int tid = threadIdx.x;
    size_t tok0 = (size_t)blockIdx.x * 128;
    int t2 = tid >> 1, kh = (tid & 1) * 64;
    const float* src = x + (tok0 + t2)*128 + kh;
    __half* dst = Xs + t2*LDX + kh;
#pragma unroll
    for (int i = 0; i < 8; i++) {
        float4 a = *(const float4*)(src + i*8);
        float4 b = *(const float4*)(src + i*8 + 4);
        *(uint4*)(dst + i*8) = make_uint4(pack2(a.x,a.y), pack2(a.z,a.w),
                                          pack2(b.x,b.y), pack2(b.z,b.w));
    }
    __syncthreads();
    gemm_pass_h<false,true>(Xs, Ws, Wq, nullptr, g_q + tok0*128, nullptr, nullptr);
    gemm_pass_h<false,true>(Xs, Ws, Wk, nullptr, g_k + tok0*128, nullptr, nullptr);
    gemm_pass_h<false,true>(Xs, Ws, Wv, nullptr, g_v + tok0*128, nullptr, nullptr);
}

__global__ void __launch_bounds__(256) vm_kernel(const float* __restrict__ bproj,
                                                 float* __restrict__ out)
{
    extern __shared__ __half smh[];
    __half* Xs = smh; __half* Ws = smh + 128*LDX;
    int tid = threadIdx.x;
    size_t tok0 = (size_t)blockIdx.x * 128;
    int b = blockIdx.x >> 9;
    int t2 = tid >> 1, kh = (tid & 1) * 64;
    const __half* src = g_v + (tok0 + t2)*128 + kh;
    __half* dst = Xs + t2*LDX + kh;
#pragma unroll
    for (int i = 0; i < 8; i++) *(uint4*)(dst + i*8) = *(const uint4*)(src + i*8);
    __syncthreads();
    gemm_pass_h<true,false>(Xs, Ws, nullptr, g_M + (size_t)b*16384,
                            nullptr, out + tok0*128, bproj);
}

// ======= attn: unchanged from passing R14/R15/R16 ============================
#define NCHUNK 16
#define LQH 40
__global__ void __launch_bounds__(256) attn_kernel()
{
    __shared__ __half qs[128*LQH];
    __shared__ __half ks[128*LQH];
    int b = blockIdx.z, h = blockIdx.y;
    int n0 = blockIdx.x * (HW_ / NCHUNK);
    int tid = threadIdx.x, lane = tid & 31, warp = tid >> 5;
    int mat = lane >> 3, rr = lane & 7;
    int r = tid >> 1, off = (tid & 1) * 16;
    int kt = warp * 16;
    float acc[2][4][4];
#pragma unroll
    for (int mt = 0; mt < 2; mt++)
#pragma unroll
        for (int nt = 0; nt < 4; nt++)
#pragma unroll
            for (int rg = 0; rg < 4; rg++) acc[mt][nt][rg] = 0.f;
    float2 ssq2[8], ssk2[8];
#pragma unroll
    for (int j = 0; j < 8; j++) { ssq2[j] = make_float2(0.f,0.f); ssk2[j] = make_float2(0.f,0.f); }

    for (int sub = 0; sub < (HW_/NCHUNK)/128; sub++) {
        int t0 = n0 + sub*128;
        size_t base = ((size_t)(b*HW_ + t0 + r))*128 + h*32 + off;
        uint4 q0 = *(const uint4*)(g_q + base);
        uint4 q1 = *(const uint4*)(g_q + base + 8);
        uint4 k0 = *(const uint4*)(g_k + base);
        uint4 k1 = *(const uint4*)(g_k + base + 8);
        *(uint4*)(qs + r*LQH + off)     = q0;
        *(uint4*)(qs + r*LQH + off + 8) = q1;
        *(uint4*)(ks + r*LQH + off)     = k0;
        *(uint4*)(ks + r*LQH + off + 8) = k1;
        {
            uint32_t uq[8] = {q0.x,q0.y,q0.z,q0.w,q1.x,q1.y,q1.z,q1.w};
            uint32_t uk[8] = {k0.x,k0.y,k0.z,k0.w,k1.x,k1.y,k1.z,k1.w};
#pragma unroll
            for (int j = 0; j < 8; j++) {
                float2 fq = __half22float2(*(__half2*)&uq[j]);
                float2 fk = __half22float2(*(__half2*)&uk[j]);
                ssq2[j].x += fq.x*fq.x; ssq2[j].y += fq.y*fq.y;
                ssk2[j].x += fk.x*fk.x; ssk2[j].y += fk.y*fk.y;
            }
        }
        __syncthreads();
        uint32_t a[2][4];
        ldsm4t(a[0], ks + (kt + (mat>>1)*8 + rr)*LQH + 0  + (mat&1)*8);
        ldsm4t(a[1], ks + (kt + (mat>>1)*8 + rr)*LQH + 16 + (mat&1)*8);
        uint32_t bfr[4][2];
#pragma unroll
        for (int eb = 0; eb < 2; eb++) {
            uint32_t r4[4];
            ldsm4t(r4, qs + (kt + (mat&1)*8 + rr)*LQH + eb*16 + (mat>>1)*8);
            bfr[eb*2][0]=r4[0]; bfr[eb*2][1]=r4[1]; bfr[eb*2+1][0]=r4[2]; bfr[eb*2+1][1]=r4[3];
        }
#pragma unroll
        for (int mt = 0; mt < 2; mt++)
#pragma unroll
            for (int nt = 0; nt < 4; nt++)
                mma16(acc[mt][nt], a[mt], bfr[nt][0], bfr[nt][1]);
        __syncthreads();
    }
    int bh = b*HEADS_ + h;
    int g2 = lane >> 2, e0 = (lane & 3)*2;
#pragma unroll
    for (int mt = 0; mt < 2; mt++)
#pragma unroll
        for (int nt = 0; nt < 4; nt++) {
            int d = mt*16 + g2, e = nt*8 + e0;
            atomicAdd(&g_attn[(bh*32 + d)*32 + e],       acc[mt][nt][0]);
            atomicAdd(&g_attn[(bh*32 + d)*32 + e + 1],   acc[mt][nt][1]);
            atomicAdd(&g_attn[(bh*32 + d+8)*32 + e],     acc[mt][nt][2]);
            atomicAdd(&g_attn[(bh*32 + d+8)*32 + e + 1], acc[mt][nt][3]);
        }
#pragma unroll
    for (int s = 2; s < 32; s <<= 1) {
#pragma unroll
        for (int j = 0; j < 8; j++) {
            ssq2[j].x += __shfl_xor_sync(~0u, ssq2[j].x, s);
            ssq2[j].y += __shfl_xor_sync(~0u, ssq2[j].y, s);
            ssk2[j].x += __shfl_xor_sync(~0u, ssk2[j].x, s);
            ssk2[j].y += __shfl_xor_sync(~0u, ssk2[j].y, s);
        }
    }
    if (lane < 2) {
#pragma unroll
        for (int j = 0; j < 8; j++) {
            atomicAdd(&g_ssq[bh*32 + off + 2*j],     ssq2[j].x);
            atomicAdd(&g_ssq[bh*32 + off + 2*j + 1], ssq2[j].y);
            atomicAdd(&g_ssk[bh*32 + off + 2*j],     ssk2[j].x);
            atomicAdd(&g_ssk[bh*32 + off + 2*j + 1], ssk2[j].y);
        }
    }
}

// ======================= softmax + M =========================================
__global__ void __launch_bounds__(1024) softmax_kernel(const float* __restrict__ rescale)
{
    int bh = blockIdx.x, h = bh & 3, tid = threadIdx.x;
    int d = tid >> 5, e = tid & 31;
    float nk = fmaxf(sqrtf(g_ssk[bh*32 + d]), 1e-12f);
    float nq = fmaxf(sqrtf(g_ssq[bh*32 + e]), 1e-12f);
    float val = g_attn[bh*1024 + d*32 + e] * rescale[h] / (nk*nq);
    float m = val;
#pragma unroll
    for (int off = 16; off > 0; off >>= 1) m = fmaxf(m, __shfl_xor_sync(~0u, m, off));
    float ex = expf(val - m);
    float s = ex;
#pragma unroll
    for (int off = 16; off > 0; off >>= 1) s += __shfl_xor_sync(~0u, s, off);
    g_attn_sm[bh*1024 + d*32 + e] = ex / s;
}

__global__ void __launch_bounds__(256) m_kernel(const float* __restrict__ Wproj)
{
    __shared__ float as[32*33];
    __shared__ float wp[32*128];
    int bh = blockIdx.x, b = bh >> 2, h = bh & 3, tid = threadIdx.x;
    for (int i = tid; i < 1024; i += 256) as[(i>>5)*33 + (i&31)] = g_attn_sm[bh*1024 + i];
    for (int i = tid; i < 1024; i += 256)
        ((float4*)wp)[i] = ((const float4*)(Wproj + (size_t)h*32*128))[i];
    __syncthreads();
    int c = tid & 127, eg = tid >> 7;
    for (int ee = 0; ee < 16; ee++) {
        int e = eg*16 + ee;
        float a = 0.f;
#pragma unroll
        for (int d = 0; d < 32; d++) a += as[d*33 + e] * wp[d*128 + c];
        g_M[(size_t)b*16384 + (h*32 + e)*128 + c] = __float2half(a);
    }
}

// ======= Gabor v4: vert direct-from-gmem (no vt), tanh-GELU, dbl-buf gh/pws ==
#define GB_TV 3584            // floats: [112][32]
#define LDG 40
#define GB_BYTES (GB_TV*4 + 2*64*LDG*2 + 2*128*LDG*2)

__global__ void __launch_bounds__(256) gabor_kernel(const float* __restrict__ dw_w,
                                                    const float* __restrict__ dw_b,
                                                    const float* __restrict__ pw_b,
                                                    float* __restrict__ out)
{
    extern __shared__ float smf[];
    float* tv = smf;                                  // [8*14][32]
    __half* gh  = (__half*)(smf + GB_TV);             // [2][64][LDG]
    __half* pws = gh + 2*64*LDG;                      // [2][128][LDG]

    int b  = blockIdx.z, y0 = blockIdx.y << 3, x0 = blockIdx.x << 3;
    int tid = threadIdx.x, lane = tid & 31, warp = tid >> 5;
    int mat = lane >> 3, rr = lane & 7;
    int wn = warp * 16;
    int c  = tid & 31, xg = tid >> 5;
    float acc[4][2][4];
#pragma unroll
    for (int mt = 0; mt < 4; mt++)
#pragma unroll
        for (int nt = 0; nt < 2; nt++)
#pragma unroll
            for (int r = 0; r < 4; r++) acc[mt][nt][r] = 0.f;

    float rowf[7];
#pragma unroll
    for (int i = 0; i < 7; i++) rowf[i] = dw_w[i*7 + 4];   // scale-independent

    for (int cg = 0; cg < 4; cg++) {
        int c0 = cg << 5;
        // --- vertical pass DIRECTLY from gmem into register window -> tv ---
        for (int xi = xg; xi < 14; xi += 8) {
            int gxx = x0 - 3 + xi;
            bool xok = (unsigned)gxx < 256u;
            const __half* vp = g_v + ((size_t)(b*HW_ + (y0-3)*256 + gxx))*128 + c0 + c;
            float w[14];
#pragma unroll
            for (int i = 0; i < 14; i++) {
                int gy = y0 - 3 + i;
                float v = 0.f;
                if (xok && (unsigned)gy < 256u)
                    v = __half2float(vp[(size_t)i*32768]);
                w[i] = v;
            }
#pragma unroll
            for (int y = 0; y < 8; y++) {
                float sum = 0.f;
#pragma unroll
                for (int i = 0; i < 7; i++) sum += rowf[i]*w[y+i];
                tv[(y*14 + xi)*32 + c] = sum;
            }
        }
        __syncthreads();
        // --- horizontal window loaded once per cg ---
        float w2[14];
#pragma unroll
        for (int xx = 0; xx < 14; xx++) w2[xx] = tv[(xg*14 + xx)*32 + c];

        for (int s = 0; s < 4; s++) {
            int p = s & 1;
            __half* ghb = gh  + p*64*LDG;
            __half* pwb = pws + p*128*LDG;
            {   // horiz + bias + tanh-GELU from registers -> ghb
                float colf[7];
#pragma unroll
                for (int j = 0; j < 7; j++) colf[j] = dw_w[s*49 + 28 + j];
                float bias = dw_b[(c0+c)*4 + s];
#pragma unroll
                for (int x = 0; x < 8; x++) {
                    float sum = bias;
#pragma unroll
                    for (int j = 0; j < 7; j++) sum += colf[j]*w2[x+j];
                    float u = 0.7978845608f*sum*(1.f + 0.044715f*sum*sum);
                    float g = 0.5f*sum*(1.f + tanh_fast(u));
                    ghb[(xg*8 + x)*LDG + c] = __float2half(g);
                }
            }
            {   // stage pw (coalesced): pwb[o][c]
                int o = tid >> 1, off = (tid & 1)*16;
                const __half* src = g_pwh + ((s*128 + o)*128) + c0 + off;
                *(uint4*)(pwb + o*LDG + off)     = *(const uint4*)src;
                *(uint4*)(pwb + o*LDG + off + 8) = *(const uint4*)(src + 8);
            }
            __syncthreads();          // single barrier per scale (double-buffered)
#pragma unroll
            for (int kc = 0; kc < 2; kc++) {
                int k0 = kc*16;
                uint32_t a[4][4];
#pragma unroll
                for (int mt = 0; mt < 4; mt++)
                    ldsm4(a[mt], ghb + (mt*16 + (mat&1)*8 + rr)*LDG + k0 + (mat>>1)*8);
                uint32_t r4[4];
                ldsm4(r4, pwb + (wn + (mat>>1)*8 + rr)*LDG + k0 + (mat&1)*8);
#pragma unroll
                for (int mt = 0; mt < 4; mt++) {
                    mma16(acc[mt][0], a[mt], r4[0], r4[1]);
                    mma16(acc[mt][1], a[mt], r4[2], r4[3]);
                }
            }
        }
        __syncthreads();   // last s's ldsm done before next cg rewrites tv/buffers
    }
    int g = lane >> 2, kq = lane & 3;
#pragma unroll
    for (int mt = 0; mt < 4; mt++)
#pragma unroll
        for (int nt = 0; nt < 2; nt++) {
            int cc = wn + nt*8 + kq*2;
            float pb0 = pw_b[cc], pb1 = pw_b[cc+1];
#pragma unroll
            for (int half = 0; half < 2; half++) {
                int pix = mt*16 + g + half*8;
                int y = pix >> 3, xx = pix & 7;
                size_t base = ((size_t)(b*HW_ + (y0+y)*256 + x0+xx))*128 + cc;
                float2 o0;
                o0.x = acc[mt][nt][half*2+0] + pb0;
                o0.y = acc[mt][nt][half*2+1] + pb1;
                *(float2*)(out + base) = o0;
            }
        }
}

// ---------------------------------------------------------------------------
extern "C" void kernel_launch(void* const* d_in, const int* in_sizes, int n_in,
                              void* d_out, int out_size)
{
    const float* x       = (const float*)d_in[0];
    const float* Wq      = (const float*)d_in[1];
    const float* Wk      = (const float*)d_in[2];
    const float* Wv      = (const float*)d_in[3];
    const float* rescale = (const float*)d_in[4];
    const float* Wproj   = (const float*)d_in[5];
    const float* bproj   = (const float*)d_in[6];
    const float* dw_w    = (const float*)d_in[7];
    const float* dw_b    = (const float*)d_in[8];
    const float* pw_w    = (const float*)d_in[9];
    const float* pw_b    = (const float*)d_in[10];
    float* out = (float*)d_out;

    cudaFuncSetAttribute(qkv_kernel, cudaFuncAttributeMaxDynamicSharedMemorySize, GEMM_SMEM);
    cudaFuncSetAttribute(vm_kernel,  cudaFuncAttributeMaxDynamicSharedMemorySize, GEMM_SMEM);
    cudaFuncSetAttribute(gabor_kernel, cudaFuncAttributeMaxDynamicSharedMemorySize, GB_BYTES);

    zero_kernel<<<64, 256>>>();                                   // idx 0
    pw_prep_kernel<<<256, 256>>>(pw_w);                           // idx 1
    qkv_kernel<<<NTOK/128, 256, GEMM_SMEM>>>(x, Wq, Wk, Wv);      // idx 2
    gabor_kernel<<<dim3(32, 32, B_), 256, GB_BYTES>>>(dw_w, dw_b, pw_b, out);  // idx 3 -> profiled
    attn_kernel<<<dim3(NCHUNK, HEADS_, B_), 256>>>();             // idx 4
    softmax_kernel<<<B_*HEADS_, 1024>>>(rescale);                 // idx 5
    m_kernel<<<B_*HEADS_, 256>>>(Wproj);                          // idx 6
    vm_kernel<<<NTOK/128, 256, GEMM_SMEM>>>(bproj, out);          // idx 7
}